// round 17
// baseline (speedup 1.0000x reference)
#include <cuda_runtime.h>
#include <cuda_bf16.h>
#include <cstdint>

#define N_NODES 50000
#define N_EDGES 800000
#define D 64
#define DH 8
#define NSEG (N_NODES * DH)

#define TM 128
#define GRID_X ((N_NODES + TM - 1) / TM)   // 391

// smem rows: 32 (hi,lo) uint2 pair-slots per row (64 k = 32 pairs), stride 34
#define SA_STRIDE 34
#define SB_STRIDE 34
#define SB_OFF (128 * SA_STRIDE)           // uint2 index of sB base
#define SMEM_BYTES ((128 * SA_STRIDE + 192 * SB_STRIDE) * 8)   // 87040

// pair-slot permutation within each 8-pair (16-k) block: thread t's pairs
// p=t and p=t+4 land in adjacent slots 2t, 2t+1 (one LDS.128 = both + hi/lo).
__device__ __forceinline__ int pslot(int p) {
    return (p & ~7) + ((p & 3) << 1) + ((p >> 2) & 1);
}

typedef unsigned long long u64;

// Device scratch (no cudaMalloc allowed)
__device__ __align__(16) float g_q[N_NODES * D];
__device__ __align__(16) float g_k[N_NODES * D];
__device__ __align__(16) float g_s[NSEG];

// (hi,lo) bf16x2 split pair for two consecutive k values (even in low half)
__device__ __forceinline__ uint2 mkpair(float e, float o) {
    __nv_bfloat162 h2 = __float22bfloat162_rn(make_float2(e, o));  // 1 packed cvt
    float2 hf = __bfloat1622float2(h2);
    __nv_bfloat162 l2 = __float22bfloat162_rn(make_float2(e - hf.x, o - hf.y));
    uint2 r;
    r.x = *(uint32_t*)&h2;
    r.y = *(uint32_t*)&l2;
    return r;
}

__device__ __forceinline__ void mma_bf16(float c[4],
                                         uint32_t a0, uint32_t a1, uint32_t a2, uint32_t a3,
                                         uint32_t b0, uint32_t b1) {
    asm volatile(
        "mma.sync.aligned.m16n8k16.row.col.f32.bf16.bf16.f32 "
        "{%0,%1,%2,%3}, {%4,%5,%6,%7}, {%8,%9}, {%0,%1,%2,%3};"
        : "+f"(c[0]), "+f"(c[1]), "+f"(c[2]), "+f"(c[3])
        : "r"(a0), "r"(a1), "r"(a2), "r"(a3), "r"(b0), "r"(b1));
}

// ---------------------------------------------------------------------------
// Tensor-core QKV GEMM, all 3 matrices per block (x converted ONCE).
// Grid (391); 384 threads = 12 warps = 4 warp-rows x 3 mats.
// Warp tile 32x64 (validated R16): m16n8k16 bf16, 2-term split, fp32 accum.
// ---------------------------------------------------------------------------
__global__ __launch_bounds__(384) void qkv_mma_kernel(
    const float* __restrict__ x,
    const float* __restrict__ Wq, const float* __restrict__ bq,
    const float* __restrict__ Wk, const float* __restrict__ bk,
    const float* __restrict__ Wv, const float* __restrict__ bv,
    float* __restrict__ vout)
{
    extern __shared__ __align__(16) uint2 smp[];
    uint2* sA = smp;            // row * SA_STRIDE + pslot(p)
    uint2* sB = smp + SB_OFF;   // (mat*64 + n) * SB_STRIDE + pslot(p)

    const int tid = threadIdx.x;
    const int n0 = blockIdx.x * TM;

    // Fused init: zero g_s (100000 float4; 391*384 = 150144 threads)
    {
        int g = blockIdx.x * 384 + tid;
        if (g < NSEG / 4) ((float4*)g_s)[g] = make_float4(0.f, 0.f, 0.f, 0.f);
    }

    // x tile: 128 rows x 64 cols -> bf16 split pairs (converted once per tile)
    {
        const float4* x4 = (const float4*)x;
#pragma unroll
        for (int i = tid; i < 2048; i += 384) {
            int row = i >> 4;
            int q4  = i & 15;
            int gn  = n0 + row;
            float4 v = (gn < N_NODES) ? x4[(size_t)gn * 16 + q4]
                                      : make_float4(0.f, 0.f, 0.f, 0.f);
            uint2* a = &sA[row * SA_STRIDE];
            a[pslot(q4 * 2)]     = mkpair(v.x, v.y);
            a[pslot(q4 * 2 + 1)] = mkpair(v.z, v.w);
        }
    }
    // W (3 mats): [k][n] row-major -> sB[mat*64+n][pslot(k/2)]
    {
#pragma unroll
        for (int i = tid; i < 6144; i += 384) {
            int mat = i >> 11;
            int rem = i & 2047;
            int p = rem >> 6;      // k-pair index
            int n = rem & 63;
            const float* W = (mat == 0) ? Wq : (mat == 1) ? Wk : Wv;
            float e = W[(2 * p) * 64 + n];
            float o = W[(2 * p + 1) * 64 + n];
            sB[(mat * 64 + n) * SB_STRIDE + pslot(p)] = mkpair(e, o);
        }
    }
    __syncthreads();

    const int wid  = tid >> 5;
    const int lane = tid & 31;
    const int wr   = wid & 3;        // warp-row 0..3
    const int mat  = wid >> 2;       // matrix 0..2
    const int g    = lane >> 2;
    const int t    = lane & 3;
    const int mrow = wr * 32;        // warp's 32-row slab

    const float* bias = (mat == 0) ? bq : (mat == 1) ? bk : bv;
    float* dst        = (mat == 0) ? g_q : (mat == 1) ? g_k : vout;
    const uint2* sBm  = sB + (mat * 64) * SB_STRIDE;

    float acc0[8][4], acc1[8][4];
#pragma unroll
    for (int n = 0; n < 8; n++)
#pragma unroll
        for (int j = 0; j < 4; j++) { acc0[n][j] = 0.f; acc1[n][j] = 0.f; }

#pragma unroll
    for (int kk = 0; kk < 4; kk++) {
        const int ks = kk * 8 + 2 * t;   // slots 2t,2t+1 = pairs p=t, p=t+4
        uint4 A0 = *(const uint4*)&sA[(mrow + g) * SA_STRIDE + ks];
        uint4 A1 = *(const uint4*)&sA[(mrow + g + 8) * SA_STRIDE + ks];
        uint4 A2 = *(const uint4*)&sA[(mrow + 16 + g) * SA_STRIDE + ks];
        uint4 A3 = *(const uint4*)&sA[(mrow + 24 + g) * SA_STRIDE + ks];
#pragma unroll
        for (int n = 0; n < 8; n++) {
            uint4 Bv = *(const uint4*)&sBm[(n * 8 + g) * SB_STRIDE + ks];
            uint32_t bh0 = Bv.x, bl0 = Bv.y, bh1 = Bv.z, bl1 = Bv.w;
            mma_bf16(acc0[n], A0.x, A1.x, A0.z, A1.z, bh0, bh1);
            mma_bf16(acc0[n], A0.x, A1.x, A0.z, A1.z, bl0, bl1);
            mma_bf16(acc0[n], A0.y, A1.y, A0.w, A1.w, bh0, bh1);
            mma_bf16(acc1[n], A2.x, A3.x, A2.z, A3.z, bh0, bh1);
            mma_bf16(acc1[n], A2.x, A3.x, A2.z, A3.z, bl0, bl1);
            mma_bf16(acc1[n], A2.y, A3.y, A2.w, A3.w, bh0, bh1);
        }
    }

    // Epilogue (validated map): rows {g,g+8}, cols {2t,2t+1}
    const int rA = n0 + mrow + g;
    const int rB = rA + 8;
    const int rC = rA + 16;
    const int rD = rA + 24;
#pragma unroll
    for (int n = 0; n < 8; n++) {
        int col = n * 8 + t * 2;
        float2 b2 = *(const float2*)&bias[col];
        if (rA < N_NODES)
            *(float2*)&dst[(size_t)rA * 64 + col] =
                make_float2(acc0[n][0] + b2.x, acc0[n][1] + b2.y);
        if (rB < N_NODES)
            *(float2*)&dst[(size_t)rB * 64 + col] =
                make_float2(acc0[n][2] + b2.x, acc0[n][3] + b2.y);
        if (rC < N_NODES)
            *(float2*)&dst[(size_t)rC * 64 + col] =
                make_float2(acc1[n][0] + b2.x, acc1[n][1] + b2.y);
        if (rD < N_NODES)
            *(float2*)&dst[(size_t)rD * 64 + col] =
                make_float2(acc1[n][2] + b2.x, acc1[n][3] + b2.y);
    }
}

// ---------------------------------------------------------------------------
// Warp-cooperative fused edge pass: logits + exp + vec4-atomic segment sum.
// 8 lanes per edge, 4 edges per warp; all gathers coalesced.
// ---------------------------------------------------------------------------
__global__ __launch_bounds__(256) void edge_fused_kernel(
    const int* __restrict__ edge, float* __restrict__ prods)
{
    const int lane = threadIdx.x & 31;
    const int warp = (blockIdx.x * 256 + threadIdx.x) >> 5;
    const int e0   = warp * 4;
    const int sub  = lane >> 3;
    const int d    = lane & 7;
    const int e    = e0 + sub;

    const int src = edge[e];
    const int dst = edge[N_EDGES + e];

    const float4* q4 = (const float4*)(g_q + src * D);
    const float4* k4 = (const float4*)(g_k + dst * D);

    float4 qa = q4[d];
    float4 qb = q4[d + 8];
    float4 ka = k4[d];
    float4 kb = k4[d + 8];

    float w0 = qa.x * ka.x + qb.x * kb.x;
    float w1 = qa.y * ka.y + qb.y * kb.y;
    float w2 = qa.z * ka.z + qb.z * kb.z;
    float w3 = qa.w * ka.w + qb.w * kb.w;

    const unsigned FULL = 0xffffffffu;

    {
        float t0 = (lane & 4) ? w0 : w2;
        float t1 = (lane & 4) ? w1 : w3;
        float u0 = __shfl_xor_sync(FULL, t0, 4);
        float u1 = __shfl_xor_sync(FULL, t1, 4);
        w0 = ((lane & 4) ? w2 : w0) + u0;
        w1 = ((lane & 4) ? w3 : w1) + u1;
    }
    float p;
    {
        float t2 = (lane & 2) ? w0 : w1;
        float u2 = __shfl_xor_sync(FULL, t2, 2);
        p = ((lane & 2) ? w1 : w0) + u2;
    }
    {
        int srcl = (sub << 3) | ((d >> 2) & 1) | ((d & 1) << 1) | ((d & 2) << 1);
        p = __shfl_sync(FULL, p, srcl);
    }

    p *= 0.35355339059327373f;  // 1/sqrt(8)

    size_t off = (size_t)e0 * 8 + lane;
    prods[off] = p;
    float ev = __expf(p);

    float p1 = __shfl_down_sync(FULL, ev, 1);
    float p2 = __shfl_down_sync(FULL, ev, 2);
    float p3 = __shfl_down_sync(FULL, ev, 3);
    if ((lane & 3) == 0) {
        float* srow = g_s + dst * 8 + (lane & 4);
        asm volatile("red.global.add.v4.f32 [%0], {%1, %2, %3, %4};"
                     :: "l"(srow), "f"(ev), "f"(p1), "f"(p2), "f"(p3) : "memory");
    }
}

// ---------------------------------------------------------------------------
// Pass C: att[e][d] = exp(prods[e][d]) / (s[dst][d] + 1e-16).
// ---------------------------------------------------------------------------
__global__ __launch_bounds__(256) void edge_scale_kernel(
    const int* __restrict__ edge, const float* __restrict__ prods,
    float* __restrict__ att)
{
    int e = blockIdx.x * blockDim.x + threadIdx.x;
    if (e >= N_EDGES) return;
    int dst = edge[N_EDGES + e];

    const float4* sr = (const float4*)(g_s + dst * 8);
    float4 s0 = sr[0];
    float4 s1 = sr[1];

    const float4* pr = (const float4*)(prods + (size_t)e * 8);
    float4 p0 = pr[0];
    float4 p1 = pr[1];

    float4 v0, v1;
    v0.x = __fdividef(__expf(p0.x), s0.x + 1e-16f);
    v0.y = __fdividef(__expf(p0.y), s0.y + 1e-16f);
    v0.z = __fdividef(__expf(p0.z), s0.z + 1e-16f);
    v0.w = __fdividef(__expf(p0.w), s0.w + 1e-16f);
    v1.x = __fdividef(__expf(p1.x), s1.x + 1e-16f);
    v1.y = __fdividef(__expf(p1.y), s1.y + 1e-16f);
    v1.z = __fdividef(__expf(p1.z), s1.z + 1e-16f);
    v1.w = __fdividef(__expf(p1.w), s1.w + 1e-16f);

    float4* ar = (float4*)(att + (size_t)e * 8);
    ar[0] = v0;
    ar[1] = v1;
}

// ---------------------------------------------------------------------------
// kernel_launch
// Inputs (metadata order): x, Wq, bq, Wk, bk, Wv, bv, edge
// Output: attention [E,8] | v [N,8,8] | prods [E,8]  (float32)
// ---------------------------------------------------------------------------
extern "C" void kernel_launch(void* const* d_in, const int* in_sizes, int n_in,
                              void* d_out, int out_size) {
    const float* x  = (const float*)d_in[0];
    const float* Wq = (const float*)d_in[1];
    const float* bq = (const float*)d_in[2];
    const float* Wk = (const float*)d_in[3];
    const float* bk = (const float*)d_in[4];
    const float* Wv = (const float*)d_in[5];
    const float* bv = (const float*)d_in[6];
    const int*   edge = (const int*)d_in[7];

    float* out   = (float*)d_out;
    float* att   = out;                          // E*8
    float* vout  = out + (size_t)N_EDGES * 8;    // N*64
    float* prods = vout + (size_t)N_NODES * 64;  // E*8

    static bool inited = false;
    if (!inited) {
        cudaFuncSetAttribute(qkv_mma_kernel,
                             cudaFuncAttributeMaxDynamicSharedMemorySize,
                             SMEM_BYTES);
        inited = true;
    }

    qkv_mma_kernel<<<GRID_X, 384, SMEM_BYTES>>>(x, Wq, bq, Wk, bk, Wv, bv, vout);
    edge_fused_kernel<<<N_EDGES / 32, 256>>>(edge, prods);
    edge_scale_kernel<<<(N_EDGES + 255) / 256, 256>>>(edge, prods, att);
}